// round 2
// baseline (speedup 1.0000x reference)
#include <cuda_runtime.h>

#define Bz 4
#define Nz 8192
#define Mz 2048
#define Kz 20
#define Cz 64
#define PTS (Bz*Mz*Kz)   // 163840

// ---------------- scratch (static device globals; no allocation) ----------------
__device__ float4 g_q[Bz*Mz];                    // sampled pts: x,y,z,|q|^2
__device__ int    g_nidx[Bz*Mz*Kz];              // knn indices
__device__ float  g_x1[(size_t)PTS*Cz];          // ~42MB
__device__ float  g_x2[(size_t)PTS*Cz];          // ~42MB
__device__ double g_sum[2*Cz];                   // per-channel sum / sumsq (re-zeroed by bnfin)
__device__ float  g_aff[3*2*Cz];                 // per-stage BN affine: a[64], c[64]

// ---------------- FPS: one block per batch, dist+points register-resident ----------------
__global__ void __launch_bounds__(1024,1) fps_kernel(const float* __restrict__ p) {
    const int b = blockIdx.x;
    const int tid = threadIdx.x;
    const float* pb = p + (size_t)b*Nz*3;
    __shared__ unsigned long long s_key[32];
    __shared__ float s_last[3];

    float px[8], py[8], pz[8], dd[8];
#pragma unroll
    for (int s = 0; s < 8; ++s) {
        int i = tid + s*1024;
        px[s] = pb[3*i+0]; py[s] = pb[3*i+1]; pz[s] = pb[3*i+2];
        dd[s] = 1e10f;
    }
    if (tid == 0) {
        float x = pb[0], y = pb[1], z = pb[2];
        float qq = __fadd_rn(__fadd_rn(__fmul_rn(x,x), __fmul_rn(y,y)), __fmul_rn(z,z));
        g_q[b*Mz] = make_float4(x, y, z, qq);
        s_last[0] = x; s_last[1] = y; s_last[2] = z;
    }
    __syncthreads();

    for (int t = 1; t < Mz; ++t) {
        const float lx = s_last[0], ly = s_last[1], lz = s_last[2];
        float bv = -1.0f; int bi = 0;
#pragma unroll
        for (int s = 0; s < 8; ++s) {
            // exact non-FMA ordering: ((dx*dx + dy*dy) + dz*dz)
            float dx = __fsub_rn(px[s], lx);
            float dy = __fsub_rn(py[s], ly);
            float dz = __fsub_rn(pz[s], lz);
            float d  = __fadd_rn(__fadd_rn(__fmul_rn(dx,dx), __fmul_rn(dy,dy)), __fmul_rn(dz,dz));
            float nd = fminf(dd[s], d);
            dd[s] = nd;
            if (nd > bv) { bv = nd; bi = tid + s*1024; }   // strict > keeps lowest index within thread
        }
        // pack: max value wins; tie -> lowest global index (dists >= 0 so float bits are monotonic)
        unsigned long long key = (((unsigned long long)__float_as_uint(bv)) << 32)
                               | (unsigned)(0xFFFFFFFFu - (unsigned)bi);
#pragma unroll
        for (int o = 16; o; o >>= 1) {
            unsigned long long ok = __shfl_down_sync(0xffffffffu, key, o);
            if (ok > key) key = ok;
        }
        if ((tid & 31) == 0) s_key[tid >> 5] = key;
        __syncthreads();
        if (tid < 32) {
            key = s_key[tid];
#pragma unroll
            for (int o = 16; o; o >>= 1) {
                unsigned long long ok = __shfl_down_sync(0xffffffffu, key, o);
                if (ok > key) key = ok;
            }
            if (tid == 0) {
                int wi = (int)(0xFFFFFFFFu - (unsigned)(key & 0xFFFFFFFFull));
                float x = pb[3*wi+0], y = pb[3*wi+1], z = pb[3*wi+2];
                float qq = __fadd_rn(__fadd_rn(__fmul_rn(x,x), __fmul_rn(y,y)), __fmul_rn(z,z));
                g_q[b*Mz + t] = make_float4(x, y, z, qq);
                s_last[0] = x; s_last[1] = y; s_last[2] = z;
            }
        }
        __syncthreads();
    }
}

// ---------------- kNN: thread per query, register-resident sorted top-20 ----------------
#define KTILE 1024
__global__ void __launch_bounds__(64) knn_kernel(const float* __restrict__ p) {
    __shared__ float4 sp[KTILE];
    const int qi = blockIdx.x*64 + threadIdx.x;      // [0, B*M)
    const int b  = qi >> 11;                         // M = 2048
    const float* pb = p + (size_t)b*Nz*3;
    const float4 q = g_q[qi];

    float nd[Kz]; int ni[Kz];
#pragma unroll
    for (int j = 0; j < Kz; ++j) { nd[j] = 1e30f; ni[j] = 0; }

    for (int t0 = 0; t0 < Nz; t0 += KTILE) {
        __syncthreads();
        for (int i = threadIdx.x; i < KTILE; i += 64) {
            float x = pb[3*(t0+i)+0], y = pb[3*(t0+i)+1], z = pb[3*(t0+i)+2];
            float pp = __fadd_rn(__fadd_rn(__fmul_rn(x,x), __fmul_rn(y,y)), __fmul_rn(z,z));
            sp[i] = make_float4(x, y, z, pp);
        }
        __syncthreads();
        float wk = nd[Kz-1];
        for (int i = 0; i < KTILE; ++i) {
            float4 pt = sp[i];
            // reference: (qq + pp) - 2*((qx*px + qy*py) + qz*pz), no FMA
            float dot = __fadd_rn(__fadd_rn(__fmul_rn(q.x,pt.x), __fmul_rn(q.y,pt.y)), __fmul_rn(q.z,pt.z));
            float d   = __fsub_rn(__fadd_rn(q.w, pt.w), __fmul_rn(2.0f, dot));
            if (d < wk) {                 // strict < : ties keep earlier (lower) index
                float cd = d; int ci = t0 + i;
#pragma unroll
                for (int j = 0; j < Kz; ++j) {
                    if (cd < nd[j]) {
                        float td = nd[j]; int ti = ni[j];
                        nd[j] = cd; ni[j] = ci; cd = td; ci = ti;
                    }
                }
                wk = nd[Kz-1];
            }
        }
    }
#pragma unroll
    for (int j = 0; j < Kz; ++j) g_nidx[(size_t)qi*Kz + j] = ni[j];
}

// ---------------- conv1: gather + [6 -> 64] matvec + leakyrelu ----------------
__global__ void __launch_bounds__(128) conv1_kernel(const float* __restrict__ p,
                                                    const float* __restrict__ W1) {
    __shared__ float sW[6][64];
    __shared__ float sf[32][8];
    const int tid = threadIdx.x;
    for (int idx = tid; idx < 384; idx += 128) {
        int c = idx / 6, j = idx - c*6;
        sW[j][c] = W1[idx];
    }
    const int gp0 = blockIdx.x * 32;
    if (tid < 32) {
        int gp = gp0 + tid;
        int m = (gp / Kz) % Mz;
        int b = gp / (Kz*Mz);
        int nid = g_nidx[gp];
        const float* pr = p + ((size_t)b*Nz + nid)*3;
        float gx = pr[0], gy = pr[1], gz = pr[2];
        float4 q = g_q[b*Mz + m];
        sf[tid][0] = __fsub_rn(gx, q.x);
        sf[tid][1] = __fsub_rn(gy, q.y);
        sf[tid][2] = __fsub_rn(gz, q.z);
        sf[tid][3] = gx; sf[tid][4] = gy; sf[tid][5] = gz;
    }
    __syncthreads();
    const int pt = tid >> 2, cg = (tid & 3) << 4;
    float f[6];
#pragma unroll
    for (int j = 0; j < 6; ++j) f[j] = sf[pt][j];
    float acc[16];
#pragma unroll
    for (int i = 0; i < 16; ++i) acc[i] = 0.f;
#pragma unroll
    for (int j = 0; j < 6; ++j)
#pragma unroll
        for (int i = 0; i < 16; ++i) acc[i] = fmaf(sW[j][cg+i], f[j], acc[i]);
    float* outp = g_x1 + (size_t)(gp0 + pt)*64 + cg;
#pragma unroll
    for (int i = 0; i < 16; ++i) {
        float v = acc[i];
        outp[i] = (v >= 0.f) ? v : 0.2f*v;
    }
}

// ---------------- conv2/3: apply prev-BN affine, [64 -> 64] matvec + leakyrelu ----------------
__global__ void __launch_bounds__(128) conv_kernel(int in_sel, const float* __restrict__ W,
                                                   int aff_stage) {
    const float* xin = in_sel ? g_x2 : g_x1;
    float*      xout = in_sel ? g_x1 : g_x2;
    __shared__ float sW[64][65];        // sW[j][c] = W[c*64+j], padded rows
    __shared__ float sx[32][65];
    __shared__ float sa[64], sc[64];
    const int tid = threadIdx.x;
    for (int idx = tid; idx < 4096; idx += 128) {
        int c = idx >> 6, j = idx & 63;
        sW[j][c] = W[idx];
    }
    if (tid < 64) {
        sa[tid] = g_aff[aff_stage*128 + tid];
        sc[tid] = g_aff[aff_stage*128 + 64 + tid];
    }
    __syncthreads();
    const int p0 = blockIdx.x * 32;
    for (int idx = tid; idx < 2048; idx += 128) {
        int j = idx & 63;
        float v = xin[(size_t)p0*64 + idx];
        sx[idx >> 6][j] = fmaf(sa[j], v, sc[j]);
    }
    __syncthreads();
    const int pt = tid >> 2, cg = (tid & 3) << 4;
    float acc[16];
#pragma unroll
    for (int i = 0; i < 16; ++i) acc[i] = 0.f;
#pragma unroll
    for (int j = 0; j < 64; ++j) {
        float xv = sx[pt][j];
#pragma unroll
        for (int i = 0; i < 16; ++i)
            acc[i] = fmaf(sW[j][cg + i], xv, acc[i]);
    }
    float* outp = xout + (size_t)(p0 + pt)*64 + cg;
#pragma unroll
    for (int i = 0; i < 16; ++i) {
        float v = acc[i];
        outp[i] = (v >= 0.f) ? v : 0.2f*v;
    }
}

// ---------------- per-channel sum/sumsq (fp32 block partials -> double atomics) ----------------
__global__ void __launch_bounds__(256) stats_kernel(int sel) {
    const float* x = sel ? g_x2 : g_x1;
    __shared__ float ssum[64], ssq[64];
    const int tid = threadIdx.x;
    if (tid < 64) { ssum[tid] = 0.f; ssq[tid] = 0.f; }
    __syncthreads();
    const int c = tid & 63;
    float sv = 0.f, sq = 0.f;
    for (int r = blockIdx.x*4 + (tid >> 6); r < PTS; r += 1024) {
        float v = x[(size_t)r*64 + c];
        sv += v; sq += v*v;
    }
    atomicAdd(&ssum[c], sv);
    atomicAdd(&ssq[c], sq);
    __syncthreads();
    if (tid < 64) {
        atomicAdd(&g_sum[tid],      (double)ssum[tid]);
        atomicAdd(&g_sum[64 + tid], (double)ssq[tid]);
    }
}

// ---------------- BN finalize: affine a,c; re-zeroes accumulators for next replay ----------------
__global__ void bnfin_kernel(int stage, const float* __restrict__ g, const float* __restrict__ bb) {
    const int c = threadIdx.x;   // 64 threads
    const double cnt = (double)PTS;
    double mean = g_sum[c] / cnt;
    double var  = g_sum[64 + c] / cnt - mean*mean;
    double inv  = 1.0 / sqrt(var + 1e-5);
    float a  = (float)((double)g[c] * inv);
    float cc = (float)((double)bb[c] - (double)a * mean);
    g_aff[stage*128 + c]      = a;
    g_aff[stage*128 + 64 + c] = cc;
    g_sum[c] = 0.0; g_sum[64 + c] = 0.0;
}

// ---------------- final: apply BN3 affine, max over K ----------------
__global__ void __launch_bounds__(256) maxk_kernel(float* __restrict__ out) {
    const int t = blockIdx.x*256 + threadIdx.x;      // [0, B*M*64)
    const int c = t & 63;
    const int m = (t >> 6) & 2047;
    const int b = t >> 17;
    const float* base = g_x1 + ((size_t)(b*Mz + m)*Kz)*64 + c;
    const float a  = g_aff[2*128 + c];
    const float cc = g_aff[2*128 + 64 + c];
    float mx = -1e30f;
#pragma unroll
    for (int k = 0; k < Kz; ++k) {
        float v = fmaf(a, base[(size_t)k*64], cc);
        mx = fmaxf(mx, v);
    }
    out[((size_t)(b*64 + c))*Mz + m] = mx;
}

// ---------------- launch ----------------
extern "C" void kernel_launch(void* const* d_in, const int* in_sizes, int n_in,
                              void* d_out, int out_size) {
    (void)in_sizes; (void)n_in; (void)out_size;
    const float* p  = (const float*)d_in[0];
    const float* W1 = (const float*)d_in[1];
    const float* g1 = (const float*)d_in[2];
    const float* b1 = (const float*)d_in[3];
    const float* W2 = (const float*)d_in[4];
    const float* g2 = (const float*)d_in[5];
    const float* b2 = (const float*)d_in[6];
    const float* W3 = (const float*)d_in[7];
    const float* g3 = (const float*)d_in[8];
    const float* b3 = (const float*)d_in[9];
    float* out = (float*)d_out;

    fps_kernel<<<Bz, 1024>>>(p);
    knn_kernel<<<(Bz*Mz)/64, 64>>>(p);
    conv1_kernel<<<PTS/32, 128>>>(p, W1);
    stats_kernel<<<256, 256>>>(0);
    bnfin_kernel<<<1, 64>>>(0, g1, b1);
    conv_kernel<<<PTS/32, 128>>>(0, W2, 0);
    stats_kernel<<<256, 256>>>(1);
    bnfin_kernel<<<1, 64>>>(1, g2, b2);
    conv_kernel<<<PTS/32, 128>>>(1, W3, 1);
    stats_kernel<<<256, 256>>>(0);
    bnfin_kernel<<<1, 64>>>(2, g3, b3);
    maxk_kernel<<<(Bz*Mz*Cz)/256, 256>>>(out);
}

// round 4
// speedup vs baseline: 1.7826x; 1.7826x over previous
#include <cuda_runtime.h>

#define Bz 4
#define Nz 8192
#define Mz 2048
#define Kz 20
#define Cz 64
#define PTS (Bz*Mz*Kz)   // 163840
#define NSLICE 8
#define SLEN 1024

typedef unsigned long long ull;

// ---------------- packed f32x2 helpers (sm_100+; only add/mul/fma exist packed) --------------
__device__ __forceinline__ ull PK(float lo, float hi) {
    ull r; asm("mov.b64 %0, {%1,%2};" : "=l"(r) : "f"(lo), "f"(hi)); return r;
}
__device__ __forceinline__ void UPK(ull v, float& lo, float& hi) {
    asm("mov.b64 {%0,%1}, %2;" : "=f"(lo), "=f"(hi) : "l"(v));
}
__device__ __forceinline__ ull ADD2(ull a, ull b) {
    ull r; asm("add.rn.f32x2 %0, %1, %2;" : "=l"(r) : "l"(a), "l"(b)); return r;
}
__device__ __forceinline__ ull MUL2(ull a, ull b) {
    ull r; asm("mul.rn.f32x2 %0, %1, %2;" : "=l"(r) : "l"(a), "l"(b)); return r;
}
__device__ __forceinline__ ull FMA2(ull a, ull b, ull c) {
    ull r; asm("fma.rn.f32x2 %0, %1, %2, %3;" : "=l"(r) : "l"(a), "l"(b), "l"(c)); return r;
}

// ---------------- scratch (static device globals; no allocation) ----------------
__device__ float4 g_q[Bz*Mz];                    // sampled pts: x,y,z,|q|^2
__device__ int    g_nidx[Bz*Mz*Kz];              // final knn indices
__device__ float  g_kd[Bz*Mz*NSLICE*Kz];         // per-slice partial top-20 dists
__device__ int    g_ki[Bz*Mz*NSLICE*Kz];         // per-slice partial top-20 idx
__device__ float  g_x1[(size_t)PTS*Cz];          // ~42MB
__device__ float  g_x2[(size_t)PTS*Cz];          // ~42MB
__device__ double g_sum[2*Cz];                   // per-channel sum / sumsq (re-zeroed by bnfin)
__device__ float  g_aff[3*2*Cz];                 // per-stage BN affine: a[64], c[64]

// ===== FPS: 256 thr/batch, 32 pts/thread, packed distances + scalar FMNMX, deferred argmax ====
extern __shared__ float fps_sm[];   // spx[8192], spy[8192], spz[8192] = 96kB

__global__ void __launch_bounds__(256,1) fps_kernel(const float* __restrict__ p) {
    const int b = blockIdx.x;
    const int tid = threadIdx.x;
    const float* pb = p + (size_t)b*Nz*3;
    float* spx = fps_sm; float* spy = fps_sm + Nz; float* spz = fps_sm + 2*Nz;
    __shared__ float s_bv[8];
    __shared__ unsigned int s_wi[2];

    for (int i = tid; i < Nz; i += 256) {
        spx[i] = pb[3*i+0]; spy[i] = pb[3*i+1]; spz[i] = pb[3*i+2];
    }
    if (tid == 0) { s_wi[0] = 0xFFFFFFFFu; s_wi[1] = 0xFFFFFFFFu; }
    __syncthreads();

    // register-resident points as 16 packed pairs; element u covers indices tid+(2u)*256, tid+(2u+1)*256
    ull px2[16], py2[16], pz2[16];
    float dd[32];
#pragma unroll
    for (int u = 0; u < 16; ++u) {
        int i0 = tid + (2*u)*256, i1 = i0 + 256;
        px2[u] = PK(spx[i0], spx[i1]);
        py2[u] = PK(spy[i0], spy[i1]);
        pz2[u] = PK(spz[i0], spz[i1]);
        dd[2*u] = 1e10f; dd[2*u+1] = 1e10f;
    }
    float lx = spx[0], ly = spy[0], lz = spz[0];
    if (tid == 0) {
        float qq = __fadd_rn(__fadd_rn(__fmul_rn(lx,lx), __fmul_rn(ly,ly)), __fmul_rn(lz,lz));
        g_q[b*Mz] = make_float4(lx, ly, lz, qq);
    }

    for (int t = 1; t < Mz; ++t) {
        const ull nx2 = PK(-lx,-lx), ny2 = PK(-ly,-ly), nz2 = PK(-lz,-lz);
        float bv = -1.0f;
#pragma unroll
        for (int u = 0; u < 16; ++u) {
            // exact per-element order: ((dx*dx + dy*dy) + dz*dz); x+(-l) == x-l bitwise
            ull dx2 = ADD2(px2[u], nx2);
            ull dy2 = ADD2(py2[u], ny2);
            ull dz2 = ADD2(pz2[u], nz2);
            ull ax = MUL2(dx2,dx2), ay = MUL2(dy2,dy2), az = MUL2(dz2,dz2);
            ull d2 = ADD2(ADD2(ax, ay), az);
            float d0, d1; UPK(d2, d0, d1);
            float n0 = fminf(dd[2*u],   d0);
            float n1 = fminf(dd[2*u+1], d1);
            dd[2*u] = n0; dd[2*u+1] = n1;
            bv = fmaxf(bv, fmaxf(n0, n1));
        }
        // warp max (all lanes keep result)
#pragma unroll
        for (int o = 16; o; o >>= 1) bv = fmaxf(bv, __shfl_xor_sync(0xffffffffu, bv, o));
        if ((tid & 31) == 0) s_bv[tid >> 5] = bv;
        __syncthreads();                               // bar 1
        float bvg = s_bv[0];
#pragma unroll
        for (int w = 1; w < 8; ++w) bvg = fmaxf(bvg, s_bv[w]);
        const int buf = t & 1;
        if (tid == 0) s_wi[buf^1] = 0xFFFFFFFFu;       // reset other buffer (safe window)
        if (bv == bvg) {
            unsigned best = 0xFFFFFFFFu;
#pragma unroll
            for (int u = 31; u >= 0; --u)              // descending: last write = lowest index
                if (dd[u] == bvg) best = (unsigned)(tid + u*256);
            atomicMin(&s_wi[buf], best);               // lowest global index wins ties
        }
        __syncthreads();                               // bar 2
        const unsigned wi = s_wi[buf];
        lx = spx[wi]; ly = spy[wi]; lz = spz[wi];
        if (tid == 0) {
            float qq = __fadd_rn(__fadd_rn(__fmul_rn(lx,lx), __fmul_rn(ly,ly)), __fmul_rn(lz,lz));
            g_q[b*Mz + t] = make_float4(lx, ly, lz, qq);
        }
    }
}

// ================= kNN: 256 queries/block x 8 point-slices, packed distances =================
__global__ void __launch_bounds__(256) knn_kernel(const float* __restrict__ p) {
    __shared__ ull spt[SLEN/2][4];      // per pair: x2,y2,z2,w2 (16kB)
    const int tid = threadIdx.x;
    const int qi = blockIdx.x*256 + tid;
    const int b  = qi >> 11;
    const float* pb = p + (size_t)b*Nz*3;
    const int t0 = blockIdx.y * SLEN;

    for (int i = tid; i < SLEN/2; i += 256) {
        int i0 = t0 + 2*i, i1 = i0 + 1;
        float x0 = pb[3*i0+0], y0 = pb[3*i0+1], z0 = pb[3*i0+2];
        float x1 = pb[3*i1+0], y1 = pb[3*i1+1], z1 = pb[3*i1+2];
        float w0 = __fadd_rn(__fadd_rn(__fmul_rn(x0,x0), __fmul_rn(y0,y0)), __fmul_rn(z0,z0));
        float w1 = __fadd_rn(__fadd_rn(__fmul_rn(x1,x1), __fmul_rn(y1,y1)), __fmul_rn(z1,z1));
        spt[i][0] = PK(x0,x1); spt[i][1] = PK(y0,y1);
        spt[i][2] = PK(z0,z1); spt[i][3] = PK(w0,w1);
    }
    __syncthreads();

    const float4 q = g_q[qi];
    const ull qx2 = PK(q.x,q.x), qy2 = PK(q.y,q.y), qz2 = PK(q.z,q.z);
    const ull qw2 = PK(q.w,q.w), n2 = PK(-2.0f,-2.0f);

    float nd[Kz]; int ni[Kz];
#pragma unroll
    for (int j = 0; j < Kz; ++j) { nd[j] = 1e30f; ni[j] = 0; }
    float wk = 1e30f;

    for (int u = 0; u < SLEN/2; ++u) {
        const ulonglong2* r = (const ulonglong2*)spt[u];
        ulonglong2 r0 = r[0], r1 = r[1];
        // d = (qq + pp) + (-2)*(((qx*px + qy*py) + qz*pz))  -- bitwise == reference order
        ull m1 = MUL2(qx2, r0.x);
        ull m2 = MUL2(qy2, r0.y);
        ull a1 = ADD2(m1, m2);
        ull m3 = MUL2(qz2, r1.x);
        ull a2 = ADD2(a1, m3);
        ull a3 = ADD2(qw2, r1.y);
        ull m4 = MUL2(a2, n2);
        ull d2 = ADD2(a3, m4);
        float d0, d1; UPK(d2, d0, d1);
        if (d0 < wk) {
            float cd = d0; int ci = t0 + 2*u;
#pragma unroll
            for (int j = 0; j < Kz; ++j)
                if (cd < nd[j]) { float td = nd[j]; int ti = ni[j]; nd[j] = cd; ni[j] = ci; cd = td; ci = ti; }
            wk = nd[Kz-1];
        }
        if (d1 < wk) {
            float cd = d1; int ci = t0 + 2*u + 1;
#pragma unroll
            for (int j = 0; j < Kz; ++j)
                if (cd < nd[j]) { float td = nd[j]; int ti = ni[j]; nd[j] = cd; ni[j] = ci; cd = td; ci = ti; }
            wk = nd[Kz-1];
        }
    }
    const size_t base = ((size_t)qi*NSLICE + blockIdx.y)*Kz;
#pragma unroll
    for (int j = 0; j < Kz; ++j) { g_kd[base+j] = nd[j]; g_ki[base+j] = ni[j]; }
}

// ---- exact 8-way merge of per-slice sorted (d, idx) lists -> global top-20 ----
__global__ void __launch_bounds__(256) kmerge_kernel() {
    const int qi = blockIdx.x*256 + threadIdx.x;
    float dc[NSLICE]; int ic[NSLICE]; int h[NSLICE];
#pragma unroll
    for (int s = 0; s < NSLICE; ++s) {
        size_t base = ((size_t)qi*NSLICE + s)*Kz;
        dc[s] = g_kd[base]; ic[s] = g_ki[base]; h[s] = 0;
    }
    for (int j = 0; j < Kz; ++j) {
        int bs = 0;
#pragma unroll
        for (int s = 1; s < NSLICE; ++s)
            if (dc[s] < dc[bs] || (dc[s] == dc[bs] && ic[s] < ic[bs])) bs = s;
        g_nidx[(size_t)qi*Kz + j] = ic[bs];
        h[bs]++;
        if (h[bs] < Kz) {
            size_t off = ((size_t)qi*NSLICE + bs)*Kz + h[bs];
            dc[bs] = g_kd[off]; ic[bs] = g_ki[off];
        } else { dc[bs] = 3.0e38f; ic[bs] = 0x7FFFFFFF; }
    }
}

// ---------------- conv1: gather + [6 -> 64] matvec + leakyrelu ----------------
__global__ void __launch_bounds__(128) conv1_kernel(const float* __restrict__ p,
                                                    const float* __restrict__ W1) {
    __shared__ float sW[6][64];
    __shared__ float sf[32][8];
    const int tid = threadIdx.x;
    for (int idx = tid; idx < 384; idx += 128) {
        int c = idx / 6, j = idx - c*6;
        sW[j][c] = W1[idx];
    }
    const int gp0 = blockIdx.x * 32;
    if (tid < 32) {
        int gp = gp0 + tid;
        int m = (gp / Kz) % Mz;
        int b = gp / (Kz*Mz);
        int nid = g_nidx[gp];
        const float* pr = p + ((size_t)b*Nz + nid)*3;
        float gx = pr[0], gy = pr[1], gz = pr[2];
        float4 q = g_q[b*Mz + m];
        sf[tid][0] = __fsub_rn(gx, q.x);
        sf[tid][1] = __fsub_rn(gy, q.y);
        sf[tid][2] = __fsub_rn(gz, q.z);
        sf[tid][3] = gx; sf[tid][4] = gy; sf[tid][5] = gz;
    }
    __syncthreads();
    const int pt = tid >> 2, cg = (tid & 3) << 4;
    float f[6];
#pragma unroll
    for (int j = 0; j < 6; ++j) f[j] = sf[pt][j];
    float acc[16];
#pragma unroll
    for (int i = 0; i < 16; ++i) acc[i] = 0.f;
#pragma unroll
    for (int j = 0; j < 6; ++j)
#pragma unroll
        for (int i = 0; i < 16; ++i) acc[i] = fmaf(sW[j][cg+i], f[j], acc[i]);
    float* outp = g_x1 + (size_t)(gp0 + pt)*64 + cg;
#pragma unroll
    for (int i = 0; i < 16; ++i) {
        float v = acc[i];
        outp[i] = (v >= 0.f) ? v : 0.2f*v;
    }
}

// ======== conv2/3: FFMA2 [64->64] matvec, 4 pts/thread, 128 pts/block ========
#define WJ 10                 // padded j-stride in u64 (16B aligned rows)
#define WCG (64*WJ + 4)       // padded cg-stride in u64 (bank stagger)
__global__ void __launch_bounds__(128) conv_kernel(int in_sel, const float* __restrict__ W,
                                                   int aff_stage) {
    const float* xin = in_sel ? g_x2 : g_x1;
    float*      xout = in_sel ? g_x1 : g_x2;
    __shared__ ull  sw[4*WCG];          // packed channel-pairs, chunk-major
    __shared__ float sx[128][65];
    __shared__ float sa[64], sc[64];
    const int tid = threadIdx.x;

    // sw[cg*WCG + j*WJ + q] = (W[c0][j], W[c0+1][j]), c0 = cg*16 + 2q
    for (int k = tid; k < 2048; k += 128) {
        int cg = k >> 9, rem = k & 511, j = rem >> 3, qq = rem & 7;
        int c0 = cg*16 + 2*qq;
        sw[cg*WCG + j*WJ + qq] = PK(W[c0*64 + j], W[(c0+1)*64 + j]);
    }
    if (tid < 64) {
        sa[tid] = g_aff[aff_stage*128 + tid];
        sc[tid] = g_aff[aff_stage*128 + 64 + tid];
    }
    __syncthreads();
    const int p0 = blockIdx.x * 128;
    for (int idx = tid; idx < 8192; idx += 128) {
        int j = idx & 63;
        float v = xin[(size_t)p0*64 + idx];
        sx[idx >> 6][j] = fmaf(sa[j], v, sc[j]);
    }
    __syncthreads();

    const int ptb = tid >> 2, cg = tid & 3;
    const ull* wbase = &sw[cg*WCG];
    ull acc[4][8];
#pragma unroll
    for (int k = 0; k < 4; ++k)
#pragma unroll
        for (int qq = 0; qq < 8; ++qq) acc[k][qq] = 0ull;

    for (int j = 0; j < 64; ++j) {
        const ulonglong2* wr = (const ulonglong2*)(wbase + j*WJ);
        ulonglong2 w01 = wr[0], w23 = wr[1], w45 = wr[2], w67 = wr[3];
        ull wv[8] = {w01.x, w01.y, w23.x, w23.y, w45.x, w45.y, w67.x, w67.y};
#pragma unroll
        for (int k = 0; k < 4; ++k) {
            float xv = sx[ptb + 32*k][j];
            ull xv2 = PK(xv, xv);
#pragma unroll
            for (int qq = 0; qq < 8; ++qq)
                acc[k][qq] = FMA2(wv[qq], xv2, acc[k][qq]);
        }
    }
#pragma unroll
    for (int k = 0; k < 4; ++k) {
        float o[16];
#pragma unroll
        for (int qq = 0; qq < 8; ++qq) {
            float lo, hi; UPK(acc[k][qq], lo, hi);
            o[2*qq]   = (lo >= 0.f) ? lo : 0.2f*lo;
            o[2*qq+1] = (hi >= 0.f) ? hi : 0.2f*hi;
        }
        float4* op = (float4*)(xout + (size_t)(p0 + ptb + 32*k)*64 + cg*16);
#pragma unroll
        for (int v4 = 0; v4 < 4; ++v4)
            op[v4] = make_float4(o[4*v4], o[4*v4+1], o[4*v4+2], o[4*v4+3]);
    }
}

// ---------------- per-channel sum/sumsq (fp32 block partials -> double atomics) --------------
__global__ void __launch_bounds__(256) stats_kernel(int sel) {
    const float* x = sel ? g_x2 : g_x1;
    __shared__ float ssum[64], ssq[64];
    const int tid = threadIdx.x;
    if (tid < 64) { ssum[tid] = 0.f; ssq[tid] = 0.f; }
    __syncthreads();
    const int c = tid & 63;
    float sv = 0.f, sq = 0.f;
    for (int r = blockIdx.x*4 + (tid >> 6); r < PTS; r += 1024) {
        float v = x[(size_t)r*64 + c];
        sv += v; sq += v*v;
    }
    atomicAdd(&ssum[c], sv);
    atomicAdd(&ssq[c], sq);
    __syncthreads();
    if (tid < 64) {
        atomicAdd(&g_sum[tid],      (double)ssum[tid]);
        atomicAdd(&g_sum[64 + tid], (double)ssq[tid]);
    }
}

// ---------------- BN finalize: affine a,c; re-zeroes accumulators for next replay ------------
__global__ void bnfin_kernel(int stage, const float* __restrict__ g, const float* __restrict__ bb) {
    const int c = threadIdx.x;   // 64 threads
    const double cnt = (double)PTS;
    double mean = g_sum[c] / cnt;
    double var  = g_sum[64 + c] / cnt - mean*mean;
    double inv  = 1.0 / sqrt(var + 1e-5);
    float a  = (float)((double)g[c] * inv);
    float cc = (float)((double)bb[c] - (double)a * mean);
    g_aff[stage*128 + c]      = a;
    g_aff[stage*128 + 64 + c] = cc;
    g_sum[c] = 0.0; g_sum[64 + c] = 0.0;
}

// ---------------- final: apply BN3 affine, max over K ----------------
__global__ void __launch_bounds__(256) maxk_kernel(float* __restrict__ out) {
    const int t = blockIdx.x*256 + threadIdx.x;      // [0, B*M*64)
    const int c = t & 63;
    const int m = (t >> 6) & 2047;
    const int b = t >> 17;
    const float* base = g_x1 + ((size_t)(b*Mz + m)*Kz)*64 + c;
    const float a  = g_aff[2*128 + c];
    const float cc = g_aff[2*128 + 64 + c];
    float mx = -1e30f;
#pragma unroll
    for (int k = 0; k < Kz; ++k) {
        float v = fmaf(a, base[(size_t)k*64], cc);
        mx = fmaxf(mx, v);
    }
    out[((size_t)(b*64 + c))*Mz + m] = mx;
}

// ---------------- launch ----------------
extern "C" void kernel_launch(void* const* d_in, const int* in_sizes, int n_in,
                              void* d_out, int out_size) {
    (void)in_sizes; (void)n_in; (void)out_size;
    const float* p  = (const float*)d_in[0];
    const float* W1 = (const float*)d_in[1];
    const float* g1 = (const float*)d_in[2];
    const float* b1 = (const float*)d_in[3];
    const float* W2 = (const float*)d_in[4];
    const float* g2 = (const float*)d_in[5];
    const float* b2 = (const float*)d_in[6];
    const float* W3 = (const float*)d_in[7];
    const float* g3 = (const float*)d_in[8];
    const float* b3 = (const float*)d_in[9];
    float* out = (float*)d_out;

    cudaFuncSetAttribute(fps_kernel, cudaFuncAttributeMaxDynamicSharedMemorySize, 3*Nz*4);

    fps_kernel<<<Bz, 256, 3*Nz*4>>>(p);
    knn_kernel<<<dim3((Bz*Mz)/256, NSLICE), 256>>>(p);
    kmerge_kernel<<<(Bz*Mz)/256, 256>>>();
    conv1_kernel<<<PTS/32, 128>>>(p, W1);
    stats_kernel<<<256, 256>>>(0);
    bnfin_kernel<<<1, 64>>>(0, g1, b1);
    conv_kernel<<<PTS/128, 128>>>(0, W2, 0);
    stats_kernel<<<256, 256>>>(1);
    bnfin_kernel<<<1, 64>>>(1, g2, b2);
    conv_kernel<<<PTS/128, 128>>>(1, W3, 1);
    stats_kernel<<<256, 256>>>(0);
    bnfin_kernel<<<1, 64>>>(2, g3, b3);
    maxk_kernel<<<(Bz*Mz*Cz)/256, 256>>>(out);
}